// round 1
// baseline (speedup 1.0000x reference)
#include <cuda_runtime.h>
#include <cuda_bf16.h>
#include <cstdint>

// ---------------------------------------------------------------------------
// GraphSAGE (2x SAGEConv mean-agg + ReLU) + linear classifier.
// N=100000 nodes, E=1600000 edges, feats=128, hidden=128, classes=64.
//
// Strategy:
//   1. Build CSR-by-dst inside the launch (deg count -> scan -> scatter).
//   2. Mean-aggregate with one 128-thread block per node (no atomics on
//      feature data; coalesced 512B gathers, L2-resident feature matrix).
//   3. Fused dual-operand SGEMM: out = relu([X|AGG] @ [Wself;Wneigh] + b),
//      128x128 block tile, 8x8 per-thread tile, weights via smem.
// ---------------------------------------------------------------------------

#define NN 100000
#define NE 1600000
#define F 128

// scratch (device globals: allocation-free rule)
__device__ int   g_deg[NN];
__device__ int   g_rowoff[NN];
__device__ int   g_cursor[NN];
__device__ int   g_csr[NE];
__device__ int   g_blocksums[128];
__device__ int   g_blockoffs[128];
__device__ float g_agg[(size_t)NN * F];
__device__ float g_h1 [(size_t)NN * F];
__device__ float g_h2 [(size_t)NN * F];

// ---------------- CSR build ----------------

__global__ void k_zero_deg(int n) {
    int i = blockIdx.x * blockDim.x + threadIdx.x;
    if (i < n) g_deg[i] = 0;
}

__global__ void k_count_deg(const int* __restrict__ dst, int e) {
    int i = blockIdx.x * blockDim.x + threadIdx.x;
    if (i < e) atomicAdd(&g_deg[dst[i]], 1);
}

// per-block exclusive scan of deg (1024/block), block totals to g_blocksums
__global__ void k_scan1(int n) {
    __shared__ int s[1024];
    int i = blockIdx.x * 1024 + threadIdx.x;
    int v = (i < n) ? g_deg[i] : 0;
    s[threadIdx.x] = v;
    __syncthreads();
#pragma unroll
    for (int off = 1; off < 1024; off <<= 1) {
        int t = (threadIdx.x >= off) ? s[threadIdx.x - off] : 0;
        __syncthreads();
        s[threadIdx.x] += t;
        __syncthreads();
    }
    if (i < n) g_rowoff[i] = s[threadIdx.x] - v;  // exclusive
    if (threadIdx.x == 1023) g_blocksums[blockIdx.x] = s[1023];
}

__global__ void k_scan2(int nb) {
    __shared__ int s[128];
    int v = (threadIdx.x < nb) ? g_blocksums[threadIdx.x] : 0;
    s[threadIdx.x] = v;
    __syncthreads();
#pragma unroll
    for (int off = 1; off < 128; off <<= 1) {
        int t = (threadIdx.x >= off) ? s[threadIdx.x - off] : 0;
        __syncthreads();
        s[threadIdx.x] += t;
        __syncthreads();
    }
    if (threadIdx.x < nb) g_blockoffs[threadIdx.x] = s[threadIdx.x] - v;  // exclusive
}

__global__ void k_scan3(int n) {
    int i = blockIdx.x * 1024 + threadIdx.x;
    if (i < n) {
        int r = g_rowoff[i] + g_blockoffs[blockIdx.x];
        g_rowoff[i] = r;
        g_cursor[i] = r;
    }
}

__global__ void k_scatter(const int* __restrict__ src, const int* __restrict__ dst, int e) {
    int i = blockIdx.x * blockDim.x + threadIdx.x;
    if (i < e) {
        int d = dst[i];
        int pos = atomicAdd(&g_cursor[d], 1);
        g_csr[pos] = src[i];
    }
}

// ---------------- mean aggregation ----------------
// one block (128 threads) per node; thread t owns feature dim t.
__global__ void k_aggregate(const float* __restrict__ feat, float* __restrict__ out) {
    int node = blockIdx.x;
    int t = threadIdx.x;
    int start = g_rowoff[node];
    int cnt = g_deg[node];
    const int* __restrict__ lst = g_csr + start;
    float acc = 0.f;
    int j = 0;
    for (; j + 4 <= cnt; j += 4) {
        int s0 = lst[j + 0];
        int s1 = lst[j + 1];
        int s2 = lst[j + 2];
        int s3 = lst[j + 3];
        float v0 = feat[(size_t)s0 * F + t];
        float v1 = feat[(size_t)s1 * F + t];
        float v2 = feat[(size_t)s2 * F + t];
        float v3 = feat[(size_t)s3 * F + t];
        acc += v0; acc += v1; acc += v2; acc += v3;
    }
    for (; j < cnt; j++) acc += feat[(size_t)lst[j] * F + t];
    float inv = (cnt > 0) ? (1.0f / (float)cnt) : 1.0f;
    out[(size_t)node * F + t] = acc * inv;
}

// ---------------- fused SGEMM ----------------
// out[M,BN] = act( X0[M,128] @ W0[128,BN] (+ X1 @ W1) + bias ), row-major.
// BM=128, BK=16, 256 threads, per-thread tile TM x TN.
template <int BN, int TM, int TN, bool RELU, int NOPS>
__global__ __launch_bounds__(256) void k_gemm(
    const float* __restrict__ X0, const float* __restrict__ X1,
    const float* __restrict__ W0, const float* __restrict__ W1,
    const float* __restrict__ bias, float* __restrict__ out, int M)
{
    constexpr int BM = 128;
    constexpr int BK = 16;
    constexpr int LDA = BM + 4;
    constexpr int CT = BN / TN;       // threads along cols
    constexpr int RT = 256 / CT;      // threads along rows
    static_assert(RT * TM == BM, "tile mismatch");

    __shared__ float As[BK * LDA];
    __shared__ float Bs[BK * BN];

    const int tid = threadIdx.x;
    const int tx = tid % CT;
    const int ty = tid / CT;
    const int row0 = blockIdx.x * BM;

    float acc[TM][TN];
#pragma unroll
    for (int i = 0; i < TM; i++)
#pragma unroll
        for (int j = 0; j < TN; j++) acc[i][j] = 0.f;

    const float* Xs[2] = {X0, X1};
    const float* Ws[2] = {W0, W1};

#pragma unroll
    for (int op = 0; op < NOPS; op++) {
        const float* __restrict__ X = Xs[op];
        const float* __restrict__ W = Ws[op];
        for (int kk = 0; kk < 128; kk += BK) {
            // A tile: 128 rows x 16 k, transposed into As[k][m]
            {
                int lr = tid >> 2;               // 0..63
                int lc = (tid & 3) << 2;         // 0,4,8,12
#pragma unroll
                for (int h = 0; h < 2; h++) {
                    int r = row0 + lr + h * 64;
                    r = (r < M) ? r : (M - 1);
                    float4 v = *reinterpret_cast<const float4*>(
                        X + (size_t)r * 128 + kk + lc);
                    int m = lr + h * 64;
                    As[(lc + 0) * LDA + m] = v.x;
                    As[(lc + 1) * LDA + m] = v.y;
                    As[(lc + 2) * LDA + m] = v.z;
                    As[(lc + 3) * LDA + m] = v.w;
                }
            }
            // B tile: 16 rows x BN (direct, coalesced)
            {
                constexpr int V = (BK * BN) / (256 * 4);  // 2 for BN=128, 1 for BN=64
#pragma unroll
                for (int h = 0; h < V; h++) {
                    int idx = (tid + h * 256) * 4;
                    int br = idx / BN;
                    int bc = idx % BN;
                    *reinterpret_cast<float4*>(&Bs[br * BN + bc]) =
                        *reinterpret_cast<const float4*>(W + (size_t)(kk + br) * BN + bc);
                }
            }
            __syncthreads();
#pragma unroll
            for (int k = 0; k < BK; k++) {
                float a[TM], b[TN];
#pragma unroll
                for (int i = 0; i < TM; i += 4)
                    *reinterpret_cast<float4*>(&a[i]) =
                        *reinterpret_cast<const float4*>(&As[k * LDA + ty * TM + i]);
#pragma unroll
                for (int j = 0; j < TN; j += 4)
                    *reinterpret_cast<float4*>(&b[j]) =
                        *reinterpret_cast<const float4*>(&Bs[k * BN + tx * TN + j]);
#pragma unroll
                for (int i = 0; i < TM; i++)
#pragma unroll
                    for (int j = 0; j < TN; j++)
                        acc[i][j] = fmaf(a[i], b[j], acc[i][j]);
            }
            __syncthreads();
        }
    }

    // epilogue
#pragma unroll
    for (int i = 0; i < TM; i++) {
        int r = row0 + ty * TM + i;
        if (r < M) {
#pragma unroll
            for (int j = 0; j < TN; j += 4) {
                int c = tx * TN + j;
                float4 v;
                v.x = acc[i][j + 0] + bias[c + 0];
                v.y = acc[i][j + 1] + bias[c + 1];
                v.z = acc[i][j + 2] + bias[c + 2];
                v.w = acc[i][j + 3] + bias[c + 3];
                if (RELU) {
                    v.x = fmaxf(v.x, 0.f); v.y = fmaxf(v.y, 0.f);
                    v.z = fmaxf(v.z, 0.f); v.w = fmaxf(v.w, 0.f);
                }
                *reinterpret_cast<float4*>(out + (size_t)r * BN + c) = v;
            }
        }
    }
}

// ---------------- launch ----------------

extern "C" void kernel_launch(void* const* d_in, const int* in_sizes, int n_in,
                              void* d_out, int out_size)
{
    const float* x      = (const float*)d_in[0];
    const float* Wself1 = (const float*)d_in[1];
    const float* Wneigh1= (const float*)d_in[2];
    const float* b1     = (const float*)d_in[3];
    const float* Wself2 = (const float*)d_in[4];
    const float* Wneigh2= (const float*)d_in[5];
    const float* b2     = (const float*)d_in[6];
    const float* Wout   = (const float*)d_in[7];
    const float* bout   = (const float*)d_in[8];
    const int* edge_src = (const int*)d_in[9];
    const int* edge_dst = (const int*)d_in[10];
    float* out = (float*)d_out;

    const int M = in_sizes[0] / F;     // 100000
    const int E = in_sizes[9];         // 1600000
    const int NB = (M + 1023) / 1024;  // scan blocks (98)

    // raw device pointers to the scratch buffers (symbols usable directly in kernels)
    // --- CSR build ---
    k_zero_deg<<<(M + 255) / 256, 256>>>(M);
    k_count_deg<<<(E + 255) / 256, 256>>>(edge_dst, E);
    k_scan1<<<NB, 1024>>>(M);
    k_scan2<<<1, 128>>>(NB);
    k_scan3<<<NB, 1024>>>(M);
    k_scatter<<<(E + 255) / 256, 256>>>(edge_src, edge_dst, E);

    // resolve symbol addresses lazily via device-side globals
    float* agg; cudaGetSymbolAddress((void**)&agg, g_agg);
    float* h1;  cudaGetSymbolAddress((void**)&h1,  g_h1);
    float* h2;  cudaGetSymbolAddress((void**)&h2,  g_h2);

    const int GB = (M + 127) / 128;    // gemm blocks (782)

    // --- layer 1 ---
    k_aggregate<<<M, 128>>>(x, agg);
    k_gemm<128, 8, 8, true, 2><<<GB, 256>>>(x, agg, Wself1, Wneigh1, b1, h1, M);

    // --- layer 2 ---
    k_aggregate<<<M, 128>>>(h1, agg);
    k_gemm<128, 8, 8, true, 2><<<GB, 256>>>(h1, agg, Wself2, Wneigh2, b2, h2, M);

    // --- classifier ---
    k_gemm<64, 4, 8, false, 1><<<GB, 256>>>(h2, nullptr, Wout, nullptr, bout, out, M);
}

// round 3
// speedup vs baseline: 1.4085x; 1.4085x over previous
#include <cuda_runtime.h>
#include <cuda_bf16.h>
#include <cstdint>

// ---------------------------------------------------------------------------
// GraphSAGE (2x SAGEConv mean-agg + ReLU) + classifier.
// tcgen05 is NOT available through this harness's compute_103 PTX pass, so
// GEMMs use warp-level mma.sync bf16 (HMMA) with a bf16x2-split K-expansion:
//   C = Ah@Bh + Al@Bh + Ah@Bl   (fp32 accumulate, ~2^-16 relative error)
// Layer GEMM:  A'[M,512]=[Xh|Xl|Gh|Gl] @ B'[128,512]=[Wsh|Wsl|Wnh|Wnl]
// Classifier:  A'[M,256]=[Hh|Hl]       @ B'[64,256] =[Woh|Wol]
// ---------------------------------------------------------------------------

#define NN 100000
#define NE 1600000
#define F 128
#define MROWS 100096  // 782 * 128

// ------------------------- device scratch ---------------------------------
__device__ int   g_deg[NN];
__device__ int   g_rowoff[NN];
__device__ int   g_cursor[NN];
__device__ int   g_csr[NE];
__device__ int   g_blocksums[128];
__device__ int   g_blockoffs[128];
__device__ __nv_bfloat16 g_A1[(size_t)MROWS * 512];  // layer1 A'; reused as classifier A' (stride 256)
__device__ __nv_bfloat16 g_A2[(size_t)MROWS * 512];  // layer2 A'
__device__ float g_h1[(size_t)MROWS * F];            // layer1 fp32 output (agg input)
__device__ __nv_bfloat16 g_B1[128 * 512];
__device__ __nv_bfloat16 g_B2[128 * 512];
__device__ __nv_bfloat16 g_Bc[64 * 256];

// chunk-pair tables (64-col chunks within A'/B')
__constant__ int c_aL[12] = {0,1, 2,3, 0,1, 4,5, 6,7, 4,5};
__constant__ int c_bL[12] = {0,1, 0,1, 2,3, 4,5, 4,5, 6,7};
__constant__ int c_aK[6]  = {0,1, 2,3, 0,1};
__constant__ int c_bK[6]  = {0,1, 0,1, 2,3};

// ------------------------- PTX helpers ------------------------------------
__device__ __forceinline__ uint32_t smem_u32(const void* p) {
    uint32_t a;
    asm("{ .reg .u64 t; cvta.to.shared.u64 t, %1; cvt.u32.u64 %0, t; }"
        : "=r"(a) : "l"(p));
    return a;
}
__device__ __forceinline__ void cp16(uint32_t s, const void* g) {
    asm volatile("cp.async.cg.shared.global [%0], [%1], 16;" :: "r"(s), "l"(g) : "memory");
}
#define CP_COMMIT() asm volatile("cp.async.commit_group;" ::: "memory")
#define CP_WAIT(n)  asm volatile("cp.async.wait_group %0;" :: "n"(n) : "memory")

__device__ __forceinline__ void ldmx4(uint32_t a, uint32_t& r0, uint32_t& r1,
                                      uint32_t& r2, uint32_t& r3) {
    asm volatile("ldmatrix.sync.aligned.m8n8.x4.shared.b16 {%0,%1,%2,%3}, [%4];"
                 : "=r"(r0), "=r"(r1), "=r"(r2), "=r"(r3) : "r"(a));
}
__device__ __forceinline__ void mma16816(float* c, uint32_t a0, uint32_t a1,
                                         uint32_t a2, uint32_t a3,
                                         uint32_t b0, uint32_t b1) {
    asm volatile("mma.sync.aligned.m16n8k16.row.col.f32.bf16.bf16.f32 "
                 "{%0,%1,%2,%3}, {%4,%5,%6,%7}, {%8,%9}, {%0,%1,%2,%3};"
                 : "+f"(c[0]), "+f"(c[1]), "+f"(c[2]), "+f"(c[3])
                 : "r"(a0), "r"(a1), "r"(a2), "r"(a3), "r"(b0), "r"(b1));
}

// ------------------------- CSR build --------------------------------------
__global__ void k_zero_deg(int n) {
    int i = blockIdx.x * blockDim.x + threadIdx.x;
    if (i < n) g_deg[i] = 0;
}
__global__ void k_count_deg(const int* __restrict__ dst, int e) {
    int i = blockIdx.x * blockDim.x + threadIdx.x;
    if (i < e) atomicAdd(&g_deg[dst[i]], 1);
}
__global__ void k_scan1(int n) {
    __shared__ int s[1024];
    int i = blockIdx.x * 1024 + threadIdx.x;
    int v = (i < n) ? g_deg[i] : 0;
    s[threadIdx.x] = v;
    __syncthreads();
#pragma unroll
    for (int off = 1; off < 1024; off <<= 1) {
        int t = (threadIdx.x >= off) ? s[threadIdx.x - off] : 0;
        __syncthreads();
        s[threadIdx.x] += t;
        __syncthreads();
    }
    if (i < n) g_rowoff[i] = s[threadIdx.x] - v;
    if (threadIdx.x == 1023) g_blocksums[blockIdx.x] = s[1023];
}
__global__ void k_scan2(int nb) {
    __shared__ int s[128];
    int v = (threadIdx.x < nb) ? g_blocksums[threadIdx.x] : 0;
    s[threadIdx.x] = v;
    __syncthreads();
#pragma unroll
    for (int off = 1; off < 128; off <<= 1) {
        int t = (threadIdx.x >= off) ? s[threadIdx.x - off] : 0;
        __syncthreads();
        s[threadIdx.x] += t;
        __syncthreads();
    }
    if (threadIdx.x < nb) g_blockoffs[threadIdx.x] = s[threadIdx.x] - v;
}
__global__ void k_scan3(int n) {
    int i = blockIdx.x * 1024 + threadIdx.x;
    if (i < n) {
        int r = g_rowoff[i] + g_blockoffs[blockIdx.x];
        g_rowoff[i] = r;
        g_cursor[i] = r;
    }
}
__global__ void k_scatter(const int* __restrict__ src, const int* __restrict__ dst, int e) {
    int i = blockIdx.x * blockDim.x + threadIdx.x;
    if (i < e) {
        int d = dst[i];
        int pos = atomicAdd(&g_cursor[d], 1);
        g_csr[pos] = src[i];
    }
}

// ------------------------- mean aggregation (writes bf16 hi/lo) -----------
__global__ void k_agg(const float* __restrict__ feat, __nv_bfloat16* __restrict__ Adst) {
    int node = blockIdx.x;
    int t = threadIdx.x;
    int start = g_rowoff[node];
    int cnt = g_deg[node];
    const int* __restrict__ lst = g_csr + start;
    float acc = 0.f;
    int j = 0;
    for (; j + 8 <= cnt; j += 8) {
        float v0 = feat[(size_t)lst[j + 0] * F + t];
        float v1 = feat[(size_t)lst[j + 1] * F + t];
        float v2 = feat[(size_t)lst[j + 2] * F + t];
        float v3 = feat[(size_t)lst[j + 3] * F + t];
        float v4 = feat[(size_t)lst[j + 4] * F + t];
        float v5 = feat[(size_t)lst[j + 5] * F + t];
        float v6 = feat[(size_t)lst[j + 6] * F + t];
        float v7 = feat[(size_t)lst[j + 7] * F + t];
        acc += v0 + v1 + v2 + v3 + v4 + v5 + v6 + v7;
    }
    for (; j < cnt; j++) acc += feat[(size_t)lst[j] * F + t];
    float v = acc * ((cnt > 0) ? (1.0f / (float)cnt) : 1.0f);
    __nv_bfloat16 hi = __float2bfloat16_rn(v);
    __nv_bfloat16 lo = __float2bfloat16_rn(v - __bfloat162float(hi));
    Adst[(size_t)node * 512 + 256 + t] = hi;  // Gh
    Adst[(size_t)node * 512 + 384 + t] = lo;  // Gl
}

// ------------------------- X -> A1' self blocks ----------------------------
__global__ void k_convertX(const float* __restrict__ x, __nv_bfloat16* __restrict__ A) {
    int idx = blockIdx.x * blockDim.x + threadIdx.x;
    if (idx >= NN * 32) return;
    int row = idx >> 5;
    int c = (idx & 31) << 2;
    float4 v = *reinterpret_cast<const float4*>(x + (size_t)row * F + c);
    __nv_bfloat16 h0 = __float2bfloat16_rn(v.x), h1 = __float2bfloat16_rn(v.y);
    __nv_bfloat16 h2 = __float2bfloat16_rn(v.z), h3 = __float2bfloat16_rn(v.w);
    __nv_bfloat16 l0 = __float2bfloat16_rn(v.x - __bfloat162float(h0));
    __nv_bfloat16 l1 = __float2bfloat16_rn(v.y - __bfloat162float(h1));
    __nv_bfloat16 l2 = __float2bfloat16_rn(v.z - __bfloat162float(h2));
    __nv_bfloat16 l3 = __float2bfloat16_rn(v.w - __bfloat162float(h3));
    __nv_bfloat162 ha = __halves2bfloat162(h0, h1), hb = __halves2bfloat162(h2, h3);
    __nv_bfloat162 la = __halves2bfloat162(l0, l1), lb = __halves2bfloat162(l2, l3);
    uint2 uh, ul;
    uh.x = *reinterpret_cast<uint32_t*>(&ha); uh.y = *reinterpret_cast<uint32_t*>(&hb);
    ul.x = *reinterpret_cast<uint32_t*>(&la); ul.y = *reinterpret_cast<uint32_t*>(&lb);
    *reinterpret_cast<uint2*>(A + (size_t)row * 512 + c) = uh;
    *reinterpret_cast<uint2*>(A + (size_t)row * 512 + 128 + c) = ul;
}

// ------------------------- weight prep (transpose + split) ----------------
__global__ void k_prepW(const float* __restrict__ Ws1, const float* __restrict__ Wn1,
                        const float* __restrict__ Ws2, const float* __restrict__ Wn2,
                        const float* __restrict__ Wo) {
    int k = blockIdx.x;      // 0..127
    int n = threadIdx.x;     // 0..127
    float v; __nv_bfloat16 h, l;
    v = Ws1[k * 128 + n]; h = __float2bfloat16_rn(v); l = __float2bfloat16_rn(v - __bfloat162float(h));
    g_B1[n * 512 + k] = h;       g_B1[n * 512 + 128 + k] = l;
    v = Wn1[k * 128 + n]; h = __float2bfloat16_rn(v); l = __float2bfloat16_rn(v - __bfloat162float(h));
    g_B1[n * 512 + 256 + k] = h; g_B1[n * 512 + 384 + k] = l;
    v = Ws2[k * 128 + n]; h = __float2bfloat16_rn(v); l = __float2bfloat16_rn(v - __bfloat162float(h));
    g_B2[n * 512 + k] = h;       g_B2[n * 512 + 128 + k] = l;
    v = Wn2[k * 128 + n]; h = __float2bfloat16_rn(v); l = __float2bfloat16_rn(v - __bfloat162float(h));
    g_B2[n * 512 + 256 + k] = h; g_B2[n * 512 + 384 + k] = l;
    if (n < 64) {
        v = Wo[k * 64 + n]; h = __float2bfloat16_rn(v); l = __float2bfloat16_rn(v - __bfloat162float(h));
        g_Bc[n * 256 + k] = h;   g_Bc[n * 256 + 128 + k] = l;
    }
}

// ------------------------- warp-MMA GEMM -----------------------------------
// D[128, N] = sum over NIT K=64 chunk pairs of A_chunk @ B_chunk^T, bias+act.
// A' rows stride ASTR elems, B' rows (n-major, k contiguous) stride BSTR.
// EPI: 0 = relu, fp32 outF (stride 128) + bf16 hi/lo outA (stride 512)
//      1 = relu, bf16 hi/lo outA (stride 256)
//      2 = none, fp32 outF (stride 64)
template <int N, int NIT, int ASTR, int BSTR, int EPI>
__global__ __launch_bounds__(256) void k_gemm_mma(
    const __nv_bfloat16* __restrict__ A, const __nv_bfloat16* __restrict__ B,
    const float* __restrict__ bias, float* __restrict__ outF,
    __nv_bfloat16* __restrict__ outA, int M)
{
    constexpr int WM = (N == 128) ? 2 : 1;   // m16 tiles per warp
    constexpr int AT = 128 * 128;            // A tile bytes
    constexpr int BT = N * 128;              // B tile bytes
    extern __shared__ char smem[];
    float* s_bias = reinterpret_cast<float*>(smem);
    const uint32_t sA0 = smem_u32(smem + 512);
    const uint32_t sB0 = sA0 + 2 * AT;

    const int tid = threadIdx.x;
    const int wid = tid >> 5, lane = tid & 31;
    const int wm = (N == 128) ? (wid >> 1) : wid;
    const int wn = (N == 128) ? (wid & 1) : 0;
    const int row0 = blockIdx.x * 128;

    if (tid < N) s_bias[tid] = bias[tid];

    const int* aC = (NIT == 12) ? c_aL : c_aK;
    const int* bC = (NIT == 12) ? c_bL : c_bK;
    const char* Ab = reinterpret_cast<const char*>(A);
    const char* Bb = reinterpret_cast<const char*>(B);

    const int g = lane >> 3, lr = lane & 7;

    float acc[WM][8][4];
#pragma unroll
    for (int i = 0; i < WM; i++)
#pragma unroll
        for (int j = 0; j < 8; j++)
#pragma unroll
            for (int k = 0; k < 4; k++) acc[i][j][k] = 0.f;

    auto load_chunk = [&](int i) {
        const int buf = i & 1;
        const int ca = aC[i], cb = bC[i];
        const uint32_t sa = sA0 + buf * AT;
#pragma unroll
        for (int t = 0; t < 4; t++) {
            int idx = tid + t * 256;
            int m = idx >> 3, u = idx & 7;
            int r = row0 + m; if (r >= M) r = M - 1;
            cp16(sa + m * 128 + ((u ^ (m & 7)) << 4),
                 Ab + ((size_t)r * ASTR + ca * 64 + u * 8) * 2);
        }
        const uint32_t sbb = sB0 + buf * BT;
#pragma unroll
        for (int t = 0; t < BT / (256 * 16); t++) {
            int idx = tid + t * 256;
            int n = idx >> 3, u = idx & 7;
            cp16(sbb + n * 128 + ((u ^ (n & 7)) << 4),
                 Bb + ((size_t)n * BSTR + cb * 64 + u * 8) * 2);
        }
        CP_COMMIT();
    };

    load_chunk(0);
    for (int i = 0; i < NIT; i++) {
        if (i + 1 < NIT) { load_chunk(i + 1); CP_WAIT(1); }
        else { CP_WAIT(0); }
        __syncthreads();
        const int buf = i & 1;
        const uint32_t sa = sA0 + buf * AT;
        const uint32_t sbb = sB0 + buf * BT;
#pragma unroll
        for (int kk = 0; kk < 4; kk++) {
            uint32_t a[WM][4];
#pragma unroll
            for (int mt = 0; mt < WM; mt++) {
                int row = wm * (WM * 16) + mt * 16 + (g & 1) * 8 + lr;
                int u = kk * 2 + (g >> 1);
                ldmx4(sa + row * 128 + ((u ^ (row & 7)) << 4),
                      a[mt][0], a[mt][1], a[mt][2], a[mt][3]);
            }
            uint32_t b[4][4];
#pragma unroll
            for (int j = 0; j < 4; j++) {
                int n = wn * 64 + j * 16 + (g >> 1) * 8 + lr;
                int u = kk * 2 + (g & 1);
                ldmx4(sbb + n * 128 + ((u ^ (n & 7)) << 4),
                      b[j][0], b[j][1], b[j][2], b[j][3]);
            }
#pragma unroll
            for (int mt = 0; mt < WM; mt++)
#pragma unroll
                for (int nt = 0; nt < 8; nt++)
                    mma16816(acc[mt][nt],
                             a[mt][0], a[mt][1], a[mt][2], a[mt][3],
                             b[nt >> 1][(nt & 1) * 2], b[nt >> 1][(nt & 1) * 2 + 1]);
        }
        __syncthreads();
    }

    // epilogue
    const int qr = lane >> 2, qc = (lane & 3) << 1;
#pragma unroll
    for (int mt = 0; mt < WM; mt++) {
#pragma unroll
        for (int h = 0; h < 2; h++) {
            int row = row0 + wm * (WM * 16) + mt * 16 + h * 8 + qr;
            if (row >= M) continue;
#pragma unroll
            for (int nt = 0; nt < 8; nt++) {
                int col = wn * 64 + nt * 8 + qc;
                float v0 = acc[mt][nt][h * 2 + 0] + s_bias[col];
                float v1 = acc[mt][nt][h * 2 + 1] + s_bias[col + 1];
                if (EPI != 2) { v0 = fmaxf(v0, 0.f); v1 = fmaxf(v1, 0.f); }
                if (EPI == 0) {
                    float2 f2 = {v0, v1};
                    *reinterpret_cast<float2*>(outF + (size_t)row * 128 + col) = f2;
                } else if (EPI == 2) {
                    float2 f2 = {v0, v1};
                    *reinterpret_cast<float2*>(outF + (size_t)row * 64 + col) = f2;
                }
                if (EPI != 2) {
                    const int ostr = (EPI == 0) ? 512 : 256;
                    __nv_bfloat16 h0 = __float2bfloat16_rn(v0);
                    __nv_bfloat16 h1 = __float2bfloat16_rn(v1);
                    __nv_bfloat16 l0 = __float2bfloat16_rn(v0 - __bfloat162float(h0));
                    __nv_bfloat16 l1 = __float2bfloat16_rn(v1 - __bfloat162float(h1));
                    __nv_bfloat162 hh = __halves2bfloat162(h0, h1);
                    __nv_bfloat162 ll = __halves2bfloat162(l0, l1);
                    *reinterpret_cast<uint32_t*>(outA + (size_t)row * ostr + col) =
                        *reinterpret_cast<uint32_t*>(&hh);
                    *reinterpret_cast<uint32_t*>(outA + (size_t)row * ostr + 128 + col) =
                        *reinterpret_cast<uint32_t*>(&ll);
                }
            }
        }
    }
}

// ------------------------- launch ------------------------------------------
extern "C" void kernel_launch(void* const* d_in, const int* in_sizes, int n_in,
                              void* d_out, int out_size) {
    const float* x       = (const float*)d_in[0];
    const float* Wself1  = (const float*)d_in[1];
    const float* Wneigh1 = (const float*)d_in[2];
    const float* b1      = (const float*)d_in[3];
    const float* Wself2  = (const float*)d_in[4];
    const float* Wneigh2 = (const float*)d_in[5];
    const float* b2      = (const float*)d_in[6];
    const float* Wout    = (const float*)d_in[7];
    const float* bout    = (const float*)d_in[8];
    const int* edge_src  = (const int*)d_in[9];
    const int* edge_dst  = (const int*)d_in[10];
    float* out = (float*)d_out;

    const int M = in_sizes[0] / F;      // 100000
    const int E = in_sizes[9];          // 1600000
    const int NB = (M + 1023) / 1024;
    const int GB = (M + 127) / 128;     // 782

    __nv_bfloat16 *A1, *A2, *B1, *B2, *Bc;
    float* h1;
    cudaGetSymbolAddress((void**)&A1, g_A1);
    cudaGetSymbolAddress((void**)&A2, g_A2);
    cudaGetSymbolAddress((void**)&B1, g_B1);
    cudaGetSymbolAddress((void**)&B2, g_B2);
    cudaGetSymbolAddress((void**)&Bc, g_Bc);
    cudaGetSymbolAddress((void**)&h1, g_h1);

    const int SMEM_L = 512 + 2 * 16384 + 2 * 128 * 128;  // 66048
    const int SMEM_C = 512 + 2 * 16384 + 2 * 64 * 128;   // 49664
    cudaFuncSetAttribute((const void*)k_gemm_mma<128, 12, 512, 512, 0>,
                         cudaFuncAttributeMaxDynamicSharedMemorySize, SMEM_L);
    cudaFuncSetAttribute((const void*)k_gemm_mma<128, 12, 512, 512, 1>,
                         cudaFuncAttributeMaxDynamicSharedMemorySize, SMEM_L);
    cudaFuncSetAttribute((const void*)k_gemm_mma<64, 6, 256, 256, 2>,
                         cudaFuncAttributeMaxDynamicSharedMemorySize, SMEM_C);

    // CSR build
    k_zero_deg<<<(M + 255) / 256, 256>>>(M);
    k_count_deg<<<(E + 255) / 256, 256>>>(edge_dst, E);
    k_scan1<<<NB, 1024>>>(M);
    k_scan2<<<1, 128>>>(NB);
    k_scan3<<<NB, 1024>>>(M);
    k_scatter<<<(E + 255) / 256, 256>>>(edge_src, edge_dst, E);

    // operand prep
    k_prepW<<<128, 128>>>(Wself1, Wneigh1, Wself2, Wneigh2, Wout);
    k_convertX<<<(NN * 32 + 255) / 256, 256>>>(x, A1);
    k_agg<<<M, 128>>>(x, A1);

    // layer 1: writes h1 (fp32) + A2 self blocks (bf16 hi/lo)
    k_gemm_mma<128, 12, 512, 512, 0><<<GB, 256, SMEM_L>>>(A1, B1, b1, h1, A2, M);

    // layer 2 aggregation into A2 neighbor blocks
    k_agg<<<M, 128>>>(h1, A2);

    // layer 2: writes classifier A' (reuse A1, stride 256)
    k_gemm_mma<128, 12, 512, 512, 1><<<GB, 256, SMEM_L>>>(A2, B2, b2, nullptr, A1, M);

    // classifier
    k_gemm_mma<64, 6, 256, 256, 2><<<GB, 256, SMEM_C>>>(A1, Bc, bout, out, nullptr, M);
}

// round 4
// speedup vs baseline: 2.2876x; 1.6242x over previous
#include <cuda_runtime.h>
#include <cuda_fp16.h>
#include <cstdint>

// ---------------------------------------------------------------------------
// GraphSAGE (2x SAGEConv mean-agg + ReLU) + classifier, fp16 HMMA edition.
// GEMMs: warp mma.sync m16n8k16 f16 (fp32 accum), fp16 2-term split:
//   C = (Ah + Al) @ W_fp16      (A split hi/lo as K-expansion, W quantized once)
// Layer GEMM:  A'[M,512]=[Xh|Xl|Gh|Gl] @ B'[128,256]=[Ws|Wn]   -> 8 K=64 chunks
// Classifier:  A'[M,256]=[Hh|Hl]       @ B'[64,128] =[Wo]      -> 4 K=64 chunks
// Aggregation: warp-per-node CSR gather, 16B per lane, shfl-broadcast indices.
// ---------------------------------------------------------------------------

#define NN 100000
#define NE 1600000
#define F 128
#define MROWS 100096  // 782 * 128

// ------------------------- device scratch ---------------------------------
__device__ int g_deg[NN];
__device__ int g_rowoff[NN];
__device__ int g_cursor[NN];
__device__ int g_csr[NE];
__device__ int g_blocksums[128];
__device__ int g_blockoffs[128];
__device__ __half g_A1[(size_t)MROWS * 512];  // layer1 A'; reused as classifier A' (stride 256)
__device__ __half g_A2[(size_t)MROWS * 512];  // layer2 A' ([Hh|Hl|Gh|Gl])
__device__ __half g_B1[128 * 256];            // [Ws1|Wn1] n-major
__device__ __half g_B2[128 * 256];            // [Ws2|Wn2]
__device__ __half g_Bc[64 * 128];             // Wo

// chunk tables: (A chunk, B chunk, load-B?) — B reused at parity distance 2
__constant__ int c_aL[8] = {0, 1, 2, 3, 4, 5, 6, 7};
__constant__ int c_bL[8] = {0, 1, 0, 1, 2, 3, 2, 3};
__constant__ int c_lL[8] = {1, 1, 0, 0, 1, 1, 0, 0};
__constant__ int c_aK[4] = {0, 1, 2, 3};
__constant__ int c_bK[4] = {0, 1, 0, 1};
__constant__ int c_lK[4] = {1, 1, 0, 0};

// ------------------------- PTX helpers ------------------------------------
__device__ __forceinline__ uint32_t smem_u32(const void* p) {
    uint32_t a;
    asm("{ .reg .u64 t; cvta.to.shared.u64 t, %1; cvt.u32.u64 %0, t; }"
        : "=r"(a) : "l"(p));
    return a;
}
__device__ __forceinline__ void cp16(uint32_t s, const void* g) {
    asm volatile("cp.async.cg.shared.global [%0], [%1], 16;" :: "r"(s), "l"(g) : "memory");
}
#define CP_COMMIT() asm volatile("cp.async.commit_group;" ::: "memory")
#define CP_WAIT(n)  asm volatile("cp.async.wait_group %0;" :: "n"(n) : "memory")

__device__ __forceinline__ void ldmx4(uint32_t a, uint32_t& r0, uint32_t& r1,
                                      uint32_t& r2, uint32_t& r3) {
    asm volatile("ldmatrix.sync.aligned.m8n8.x4.shared.b16 {%0,%1,%2,%3}, [%4];"
                 : "=r"(r0), "=r"(r1), "=r"(r2), "=r"(r3) : "r"(a));
}
__device__ __forceinline__ void mma16816(float* c, uint32_t a0, uint32_t a1,
                                         uint32_t a2, uint32_t a3,
                                         uint32_t b0, uint32_t b1) {
    asm volatile("mma.sync.aligned.m16n8k16.row.col.f32.f16.f16.f32 "
                 "{%0,%1,%2,%3}, {%4,%5,%6,%7}, {%8,%9}, {%0,%1,%2,%3};"
                 : "+f"(c[0]), "+f"(c[1]), "+f"(c[2]), "+f"(c[3])
                 : "r"(a0), "r"(a1), "r"(a2), "r"(a3), "r"(b0), "r"(b1));
}

// pack 2 floats -> (hi half2 bits, lo half2 bits)
__device__ __forceinline__ void split2(float v0, float v1, uint32_t& hi, uint32_t& lo) {
    __half h0 = __float2half_rn(v0), h1 = __float2half_rn(v1);
    __half l0 = __float2half_rn(v0 - __half2float(h0));
    __half l1 = __float2half_rn(v1 - __half2float(h1));
    __half2 hh = __halves2half2(h0, h1), ll = __halves2half2(l0, l1);
    hi = *reinterpret_cast<uint32_t*>(&hh);
    lo = *reinterpret_cast<uint32_t*>(&ll);
}

// ------------------------- CSR build --------------------------------------
__global__ void k_zero_deg(int n) {
    int i = blockIdx.x * blockDim.x + threadIdx.x;
    if (i < n) g_deg[i] = 0;
}
__global__ void k_count_deg(const int* __restrict__ dst, int e) {
    int i = blockIdx.x * blockDim.x + threadIdx.x;
    if (i < e) atomicAdd(&g_deg[dst[i]], 1);
}
__global__ void k_scan1(int n) {
    __shared__ int s[1024];
    int i = blockIdx.x * 1024 + threadIdx.x;
    int v = (i < n) ? g_deg[i] : 0;
    s[threadIdx.x] = v;
    __syncthreads();
#pragma unroll
    for (int off = 1; off < 1024; off <<= 1) {
        int t = (threadIdx.x >= off) ? s[threadIdx.x - off] : 0;
        __syncthreads();
        s[threadIdx.x] += t;
        __syncthreads();
    }
    if (i < n) g_rowoff[i] = s[threadIdx.x] - v;
    if (threadIdx.x == 1023) g_blocksums[blockIdx.x] = s[1023];
}
__global__ void k_scan2(int nb) {
    __shared__ int s[128];
    int v = (threadIdx.x < nb) ? g_blocksums[threadIdx.x] : 0;
    s[threadIdx.x] = v;
    __syncthreads();
#pragma unroll
    for (int off = 1; off < 128; off <<= 1) {
        int t = (threadIdx.x >= off) ? s[threadIdx.x - off] : 0;
        __syncthreads();
        s[threadIdx.x] += t;
        __syncthreads();
    }
    if (threadIdx.x < nb) g_blockoffs[threadIdx.x] = s[threadIdx.x] - v;
}
__global__ void k_scan3(int n) {
    int i = blockIdx.x * 1024 + threadIdx.x;
    if (i < n) {
        int r = g_rowoff[i] + g_blockoffs[blockIdx.x];
        g_rowoff[i] = r;
        g_cursor[i] = r;
    }
}
__global__ void k_scatter(const int* __restrict__ src, const int* __restrict__ dst, int e) {
    int i = blockIdx.x * blockDim.x + threadIdx.x;
    if (i < e) {
        int d = dst[i];
        int pos = atomicAdd(&g_cursor[d], 1);
        g_csr[pos] = src[i];
    }
}

// ------------------------- aggregation (warp per node) --------------------
// Gh/Gl written at cols 256/384 of Adst (stride 512).
__global__ void k_agg_f32(const float* __restrict__ feat, __half* __restrict__ Adst) {
    int node = (blockIdx.x * blockDim.x + threadIdx.x) >> 5;
    if (node >= NN) return;
    int lane = threadIdx.x & 31;
    int start = g_rowoff[node], cnt = g_deg[node];
    float a0 = 0.f, a1 = 0.f, a2 = 0.f, a3 = 0.f;
    for (int j = 0; j < cnt; j += 32) {
        int myi = (j + lane < cnt) ? g_csr[start + j + lane] : 0;
        int nj = min(32, cnt - j);
        for (int k = 0; k < nj; k++) {
            int s = __shfl_sync(0xffffffffu, myi, k);
            float4 v = *reinterpret_cast<const float4*>(feat + (size_t)s * F + (lane << 2));
            a0 += v.x; a1 += v.y; a2 += v.z; a3 += v.w;
        }
    }
    float inv = (cnt > 0) ? (1.0f / (float)cnt) : 1.0f;
    a0 *= inv; a1 *= inv; a2 *= inv; a3 *= inv;
    uint2 hi, lo;
    split2(a0, a1, hi.x, lo.x);
    split2(a2, a3, hi.y, lo.y);
    *reinterpret_cast<uint2*>(Adst + (size_t)node * 512 + 256 + (lane << 2)) = hi;
    *reinterpret_cast<uint2*>(Adst + (size_t)node * 512 + 384 + (lane << 2)) = lo;
}

// layer2: input features reconstructed from hi/lo halves in H (stride 512, hi@0, lo@128)
__global__ void k_agg_hl(const __half* __restrict__ H, __half* __restrict__ Adst) {
    int node = (blockIdx.x * blockDim.x + threadIdx.x) >> 5;
    if (node >= NN) return;
    int lane = threadIdx.x & 31;
    int start = g_rowoff[node], cnt = g_deg[node];
    float a0 = 0.f, a1 = 0.f, a2 = 0.f, a3 = 0.f;
    for (int j = 0; j < cnt; j += 32) {
        int myi = (j + lane < cnt) ? g_csr[start + j + lane] : 0;
        int nj = min(32, cnt - j);
        for (int k = 0; k < nj; k++) {
            int s = __shfl_sync(0xffffffffu, myi, k);
            const __half* row = H + (size_t)s * 512 + (lane << 2);
            uint2 hu = *reinterpret_cast<const uint2*>(row);
            uint2 lu = *reinterpret_cast<const uint2*>(row + 128);
            __half2 h01 = *reinterpret_cast<__half2*>(&hu.x);
            __half2 h23 = *reinterpret_cast<__half2*>(&hu.y);
            __half2 l01 = *reinterpret_cast<__half2*>(&lu.x);
            __half2 l23 = *reinterpret_cast<__half2*>(&lu.y);
            float2 fh01 = __half22float2(h01), fh23 = __half22float2(h23);
            float2 fl01 = __half22float2(l01), fl23 = __half22float2(l23);
            a0 += fh01.x + fl01.x; a1 += fh01.y + fl01.y;
            a2 += fh23.x + fl23.x; a3 += fh23.y + fl23.y;
        }
    }
    float inv = (cnt > 0) ? (1.0f / (float)cnt) : 1.0f;
    a0 *= inv; a1 *= inv; a2 *= inv; a3 *= inv;
    uint2 hi, lo;
    split2(a0, a1, hi.x, lo.x);
    split2(a2, a3, hi.y, lo.y);
    *reinterpret_cast<uint2*>(Adst + (size_t)node * 512 + 256 + (lane << 2)) = hi;
    *reinterpret_cast<uint2*>(Adst + (size_t)node * 512 + 384 + (lane << 2)) = lo;
}

// ------------------------- X -> A1' self blocks ----------------------------
__global__ void k_convertX(const float* __restrict__ x, __half* __restrict__ A) {
    int idx = blockIdx.x * blockDim.x + threadIdx.x;
    if (idx >= NN * 32) return;
    int row = idx >> 5;
    int c = (idx & 31) << 2;
    float4 v = *reinterpret_cast<const float4*>(x + (size_t)row * F + c);
    uint2 hi, lo;
    split2(v.x, v.y, hi.x, lo.x);
    split2(v.z, v.w, hi.y, lo.y);
    *reinterpret_cast<uint2*>(A + (size_t)row * 512 + c) = hi;         // Xh
    *reinterpret_cast<uint2*>(A + (size_t)row * 512 + 128 + c) = lo;   // Xl
}

// ------------------------- weight prep (transpose, fp16) ------------------
__global__ void k_prepW(const float* __restrict__ Ws1, const float* __restrict__ Wn1,
                        const float* __restrict__ Ws2, const float* __restrict__ Wn2,
                        const float* __restrict__ Wo) {
    int k = blockIdx.x;   // 0..127
    int n = threadIdx.x;  // 0..127
    g_B1[n * 256 + k]       = __float2half_rn(Ws1[k * 128 + n]);
    g_B1[n * 256 + 128 + k] = __float2half_rn(Wn1[k * 128 + n]);
    g_B2[n * 256 + k]       = __float2half_rn(Ws2[k * 128 + n]);
    g_B2[n * 256 + 128 + k] = __float2half_rn(Wn2[k * 128 + n]);
    if (n < 64) g_Bc[n * 128 + k] = __float2half_rn(Wo[k * 64 + n]);
}

// ------------------------- warp-MMA GEMM -----------------------------------
// D[128, N] = sum over NIT K=64 chunks of A_chunk @ B_chunk^T, bias (+relu).
// EPI: 1 = relu, fp16 hi/lo to outA (row stride OSTR, lo at +128)
//      2 = none, fp32 to outF (row stride 64)
template <int N, int NIT, int ASTR, int BSTR, int EPI, int OSTR>
__global__ __launch_bounds__(256) void k_gemm_mma(
    const __half* __restrict__ A, const __half* __restrict__ B,
    const float* __restrict__ bias, float* __restrict__ outF,
    __half* __restrict__ outA, int M)
{
    constexpr int WM = (N == 128) ? 2 : 1;
    constexpr int AT = 128 * 128;   // bytes per A stage
    constexpr int BT = N * 128;     // bytes per B stage
    extern __shared__ char smem[];
    float* s_bias = reinterpret_cast<float*>(smem);
    const uint32_t sA0 = smem_u32(smem + 512);
    const uint32_t sB0 = sA0 + 2 * AT;

    const int tid = threadIdx.x;
    const int wid = tid >> 5, lane = tid & 31;
    const int wm = (N == 128) ? (wid >> 1) : wid;
    const int wn = (N == 128) ? (wid & 1) : 0;
    const int row0 = blockIdx.x * 128;

    if (tid < N) s_bias[tid] = bias[tid];

    const int* aC = (NIT == 8) ? c_aL : c_aK;
    const int* bC = (NIT == 8) ? c_bL : c_bK;
    const int* lB = (NIT == 8) ? c_lL : c_lK;
    const char* Ab = reinterpret_cast<const char*>(A);
    const char* Bb = reinterpret_cast<const char*>(B);
    const int g = lane >> 3, lr = lane & 7;

    float acc[WM][8][4];
#pragma unroll
    for (int i = 0; i < WM; i++)
#pragma unroll
        for (int j = 0; j < 8; j++)
#pragma unroll
            for (int k = 0; k < 4; k++) acc[i][j][k] = 0.f;

    auto load_chunk = [&](int i) {
        const int buf = i & 1;
        const uint32_t sa = sA0 + buf * AT;
        const int ca = aC[i];
#pragma unroll
        for (int t = 0; t < 4; t++) {
            int idx = tid + t * 256;
            int m = idx >> 3, u = idx & 7;
            int r = row0 + m; if (r >= M) r = M - 1;
            cp16(sa + m * 128 + ((u ^ (m & 7)) << 4),
                 Ab + ((size_t)r * ASTR + ca * 64 + u * 8) * 2);
        }
        if (lB[i]) {
            const uint32_t sbb = sB0 + buf * BT;
            const int cb = bC[i];
#pragma unroll
            for (int t = 0; t < BT / (256 * 16); t++) {
                int idx = tid + t * 256;
                int n = idx >> 3, u = idx & 7;
                cp16(sbb + n * 128 + ((u ^ (n & 7)) << 4),
                     Bb + ((size_t)n * BSTR + cb * 64 + u * 8) * 2);
            }
        }
        CP_COMMIT();
    };

    load_chunk(0);
    for (int i = 0; i < NIT; i++) {
        if (i + 1 < NIT) { load_chunk(i + 1); CP_WAIT(1); }
        else { CP_WAIT(0); }
        __syncthreads();
        const int buf = i & 1;
        const uint32_t sa = sA0 + buf * AT;
        const uint32_t sbb = sB0 + buf * BT;
#pragma unroll
        for (int kk = 0; kk < 4; kk++) {
            uint32_t a[WM][4];
#pragma unroll
            for (int mt = 0; mt < WM; mt++) {
                int row = wm * (WM * 16) + mt * 16 + (g & 1) * 8 + lr;
                int u = kk * 2 + (g >> 1);
                ldmx4(sa + row * 128 + ((u ^ (row & 7)) << 4),
                      a[mt][0], a[mt][1], a[mt][2], a[mt][3]);
            }
            uint32_t b[4][4];
#pragma unroll
            for (int j = 0; j < 4; j++) {
                int n = wn * 64 + j * 16 + (g >> 1) * 8 + lr;
                int u = kk * 2 + (g & 1);
                ldmx4(sbb + n * 128 + ((u ^ (n & 7)) << 4),
                      b[j][0], b[j][1], b[j][2], b[j][3]);
            }
#pragma unroll
            for (int mt = 0; mt < WM; mt++)
#pragma unroll
                for (int nt = 0; nt < 8; nt++)
                    mma16816(acc[mt][nt],
                             a[mt][0], a[mt][1], a[mt][2], a[mt][3],
                             b[nt >> 1][(nt & 1) * 2], b[nt >> 1][(nt & 1) * 2 + 1]);
        }
        __syncthreads();
    }

    // epilogue
    const int qr = lane >> 2, qc = (lane & 3) << 1;
#pragma unroll
    for (int mt = 0; mt < WM; mt++) {
#pragma unroll
        for (int h = 0; h < 2; h++) {
            int row = row0 + wm * (WM * 16) + mt * 16 + h * 8 + qr;
            if (row >= M) continue;
#pragma unroll
            for (int nt = 0; nt < 8; nt++) {
                int col = wn * 64 + nt * 8 + qc;
                float v0 = acc[mt][nt][h * 2 + 0] + s_bias[col];
                float v1 = acc[mt][nt][h * 2 + 1] + s_bias[col + 1];
                if (EPI == 1) {
                    v0 = fmaxf(v0, 0.f); v1 = fmaxf(v1, 0.f);
                    uint32_t hi, lo;
                    split2(v0, v1, hi, lo);
                    *reinterpret_cast<uint32_t*>(outA + (size_t)row * OSTR + col) = hi;
                    *reinterpret_cast<uint32_t*>(outA + (size_t)row * OSTR + 128 + col) = lo;
                } else {
                    float2 f2 = {v0, v1};
                    *reinterpret_cast<float2*>(outF + (size_t)row * 64 + col) = f2;
                }
            }
        }
    }
}

// ------------------------- launch ------------------------------------------
extern "C" void kernel_launch(void* const* d_in, const int* in_sizes, int n_in,
                              void* d_out, int out_size) {
    const float* x       = (const float*)d_in[0];
    const float* Wself1  = (const float*)d_in[1];
    const float* Wneigh1 = (const float*)d_in[2];
    const float* b1      = (const float*)d_in[3];
    const float* Wself2  = (const float*)d_in[4];
    const float* Wneigh2 = (const float*)d_in[5];
    const float* b2      = (const float*)d_in[6];
    const float* Wout    = (const float*)d_in[7];
    const float* bout    = (const float*)d_in[8];
    const int* edge_src  = (const int*)d_in[9];
    const int* edge_dst  = (const int*)d_in[10];
    float* out = (float*)d_out;

    const int M = in_sizes[0] / F;      // 100000
    const int E = in_sizes[9];          // 1600000
    const int NB = (M + 1023) / 1024;
    const int GB = (M + 127) / 128;     // 782
    const int AGGB = (M * 32 + 255) / 256;

    __half *A1, *A2, *B1, *B2, *Bc;
    cudaGetSymbolAddress((void**)&A1, g_A1);
    cudaGetSymbolAddress((void**)&A2, g_A2);
    cudaGetSymbolAddress((void**)&B1, g_B1);
    cudaGetSymbolAddress((void**)&B2, g_B2);
    cudaGetSymbolAddress((void**)&Bc, g_Bc);

    const int SMEM_L = 512 + 2 * 16384 + 2 * 128 * 128;  // 66048
    const int SMEM_C = 512 + 2 * 16384 + 2 * 64 * 128;   // 49664
    cudaFuncSetAttribute((const void*)k_gemm_mma<128, 8, 512, 256, 1, 512>,
                         cudaFuncAttributeMaxDynamicSharedMemorySize, SMEM_L);
    cudaFuncSetAttribute((const void*)k_gemm_mma<128, 8, 512, 256, 1, 256>,
                         cudaFuncAttributeMaxDynamicSharedMemorySize, SMEM_L);
    cudaFuncSetAttribute((const void*)k_gemm_mma<64, 4, 256, 128, 2, 0>,
                         cudaFuncAttributeMaxDynamicSharedMemorySize, SMEM_C);

    // CSR build
    k_zero_deg<<<(M + 255) / 256, 256>>>(M);
    k_count_deg<<<(E + 255) / 256, 256>>>(edge_dst, E);
    k_scan1<<<NB, 1024>>>(M);
    k_scan2<<<1, 128>>>(NB);
    k_scan3<<<NB, 1024>>>(M);
    k_scatter<<<(E + 255) / 256, 256>>>(edge_src, edge_dst, E);

    // operand prep
    k_prepW<<<128, 128>>>(Wself1, Wneigh1, Wself2, Wneigh2, Wout);
    k_convertX<<<(NN * 32 + 255) / 256, 256>>>(x, A1);
    k_agg_f32<<<AGGB, 256>>>(x, A1);

    // layer 1: writes A2 self blocks [Hh|Hl] (stride 512)
    k_gemm_mma<128, 8, 512, 256, 1, 512><<<GB, 256, SMEM_L>>>(A1, B1, b1, nullptr, A2, M);

    // layer 2 aggregation (reads A2 hi/lo, writes A2 G blocks)
    k_agg_hl<<<AGGB, 256>>>(A2, A2);

    // layer 2: writes classifier A' into A1 (stride 256)
    k_gemm_mma<128, 8, 512, 256, 1, 256><<<GB, 256, SMEM_L>>>(A2, B2, b2, nullptr, A1, M);

    // classifier
    k_gemm_mma<64, 4, 256, 128, 2, 0><<<GB, 256, SMEM_C>>>(A1, Bc, bout, out, nullptr, M);
}

// round 5
// speedup vs baseline: 2.3384x; 1.0222x over previous
#include <cuda_runtime.h>
#include <cuda_fp16.h>
#include <cstdint>

// ---------------------------------------------------------------------------
// GraphSAGE (2x SAGEConv mean-agg + ReLU) + classifier, fp16 HMMA edition.
//   C = (Ah + Al) @ W_fp16  (A hi/lo split as K-expansion, W quantized once)
// Aggregations gather only hi halves (256B/row), accumulate fp32, re-split.
// GEMM: B' fully resident in smem; A chunks double-buffered via cp.async.
// ---------------------------------------------------------------------------

#define NN 100000
#define NE 1600000
#define F 128
#define MROWS 100096  // 782 * 128

// ------------------------- device scratch ---------------------------------
__device__ int g_deg[NN];
__device__ int g_rowoff[NN];
__device__ int g_cursor[NN];
__device__ int g_csr[NE];
__device__ int g_blocksums[128];
__device__ int g_blockoffs[128];
__device__ __half g_A1[(size_t)MROWS * 512];  // [Xh|Xl|Gh|Gl]; reused as classifier A' (stride 256)
__device__ __half g_A2[(size_t)MROWS * 512];  // [Hh|Hl|Gh|Gl]
__device__ __half g_B1[128 * 256];            // [Ws1|Wn1] n-major
__device__ __half g_B2[128 * 256];            // [Ws2|Wn2]
__device__ __half g_Bc[64 * 128];             // Wo

// chunk tables: A chunk index, B chunk index per iteration
__constant__ int c_aL[8] = {0, 1, 2, 3, 4, 5, 6, 7};
__constant__ int c_bL[8] = {0, 1, 0, 1, 2, 3, 2, 3};
__constant__ int c_aK[4] = {0, 1, 2, 3};
__constant__ int c_bK[4] = {0, 1, 0, 1};

// ------------------------- PTX helpers ------------------------------------
__device__ __forceinline__ uint32_t smem_u32(const void* p) {
    uint32_t a;
    asm("{ .reg .u64 t; cvta.to.shared.u64 t, %1; cvt.u32.u64 %0, t; }"
        : "=r"(a) : "l"(p));
    return a;
}
__device__ __forceinline__ void cp16(uint32_t s, const void* g) {
    asm volatile("cp.async.cg.shared.global [%0], [%1], 16;" :: "r"(s), "l"(g) : "memory");
}
#define CP_COMMIT() asm volatile("cp.async.commit_group;" ::: "memory")
#define CP_WAIT(n)  asm volatile("cp.async.wait_group %0;" :: "n"(n) : "memory")

__device__ __forceinline__ void ldmx4(uint32_t a, uint32_t& r0, uint32_t& r1,
                                      uint32_t& r2, uint32_t& r3) {
    asm volatile("ldmatrix.sync.aligned.m8n8.x4.shared.b16 {%0,%1,%2,%3}, [%4];"
                 : "=r"(r0), "=r"(r1), "=r"(r2), "=r"(r3) : "r"(a));
}
__device__ __forceinline__ void mma16816(float* c, uint32_t a0, uint32_t a1,
                                         uint32_t a2, uint32_t a3,
                                         uint32_t b0, uint32_t b1) {
    asm volatile("mma.sync.aligned.m16n8k16.row.col.f32.f16.f16.f32 "
                 "{%0,%1,%2,%3}, {%4,%5,%6,%7}, {%8,%9}, {%0,%1,%2,%3};"
                 : "+f"(c[0]), "+f"(c[1]), "+f"(c[2]), "+f"(c[3])
                 : "r"(a0), "r"(a1), "r"(a2), "r"(a3), "r"(b0), "r"(b1));
}
__device__ __forceinline__ void split2(float v0, float v1, uint32_t& hi, uint32_t& lo) {
    __half h0 = __float2half_rn(v0), h1 = __float2half_rn(v1);
    __half l0 = __float2half_rn(v0 - __half2float(h0));
    __half l1 = __float2half_rn(v1 - __half2float(h1));
    __half2 hh = __halves2half2(h0, h1), ll = __halves2half2(l0, l1);
    hi = *reinterpret_cast<uint32_t*>(&hh);
    lo = *reinterpret_cast<uint32_t*>(&ll);
}

// ------------------------- CSR build --------------------------------------
__global__ void k_count_deg(const int* __restrict__ dst, int e) {
    int i = blockIdx.x * blockDim.x + threadIdx.x;
    if (i < e) atomicAdd(&g_deg[dst[i]], 1);
}
__global__ void k_scan1(int n) {
    __shared__ int s[1024];
    int i = blockIdx.x * 1024 + threadIdx.x;
    int v = (i < n) ? g_deg[i] : 0;
    s[threadIdx.x] = v;
    __syncthreads();
#pragma unroll
    for (int off = 1; off < 1024; off <<= 1) {
        int t = (threadIdx.x >= off) ? s[threadIdx.x - off] : 0;
        __syncthreads();
        s[threadIdx.x] += t;
        __syncthreads();
    }
    if (i < n) g_rowoff[i] = s[threadIdx.x] - v;
    if (threadIdx.x == 1023) g_blocksums[blockIdx.x] = s[1023];
}
__global__ void k_scan2(int nb) {
    __shared__ int s[128];
    int v = (threadIdx.x < nb) ? g_blocksums[threadIdx.x] : 0;
    s[threadIdx.x] = v;
    __syncthreads();
#pragma unroll
    for (int off = 1; off < 128; off <<= 1) {
        int t = (threadIdx.x >= off) ? s[threadIdx.x - off] : 0;
        __syncthreads();
        s[threadIdx.x] += t;
        __syncthreads();
    }
    if (threadIdx.x < nb) g_blockoffs[threadIdx.x] = s[threadIdx.x] - v;
}
__global__ void k_scan3(int n) {
    int i = blockIdx.x * 1024 + threadIdx.x;
    if (i < n) {
        int r = g_rowoff[i] + g_blockoffs[blockIdx.x];
        g_rowoff[i] = r;
        g_cursor[i] = r;
    }
}
__global__ void k_scatter(const int* __restrict__ src, const int* __restrict__ dst, int e) {
    int i = blockIdx.x * blockDim.x + threadIdx.x;
    if (i < e) {
        int d = dst[i];
        int pos = atomicAdd(&g_cursor[d], 1);
        g_csr[pos] = src[i];
    }
}

// ------------------------- aggregation (warp per node, hi-only gather) ----
// Reads hi block (offset 0, row stride 512 halves) of Hsrc; accumulates fp32;
// writes exact hi/lo split of the mean to cols 256/384 of Adst (stride 512).
__global__ void k_agg(const __half* __restrict__ Hsrc, __half* __restrict__ Adst) {
    int node = (blockIdx.x * blockDim.x + threadIdx.x) >> 5;
    if (node >= NN) return;
    int lane = threadIdx.x & 31;
    int start = g_rowoff[node], cnt = g_deg[node];
    float a0 = 0.f, a1 = 0.f, a2 = 0.f, a3 = 0.f;
    for (int j = 0; j < cnt; j += 32) {
        int myi = (j + lane < cnt) ? g_csr[start + j + lane] : 0;
        int nj = min(32, cnt - j);
        int k = 0;
        for (; k + 2 <= nj; k += 2) {
            int s0 = __shfl_sync(0xffffffffu, myi, k);
            int s1 = __shfl_sync(0xffffffffu, myi, k + 1);
            uint2 u0 = *reinterpret_cast<const uint2*>(Hsrc + (size_t)s0 * 512 + (lane << 2));
            uint2 u1 = *reinterpret_cast<const uint2*>(Hsrc + (size_t)s1 * 512 + (lane << 2));
            float2 p0 = __half22float2(*reinterpret_cast<__half2*>(&u0.x));
            float2 p1 = __half22float2(*reinterpret_cast<__half2*>(&u0.y));
            float2 q0 = __half22float2(*reinterpret_cast<__half2*>(&u1.x));
            float2 q1 = __half22float2(*reinterpret_cast<__half2*>(&u1.y));
            a0 += p0.x + q0.x; a1 += p0.y + q0.y;
            a2 += p1.x + q1.x; a3 += p1.y + q1.y;
        }
        for (; k < nj; k++) {
            int s = __shfl_sync(0xffffffffu, myi, k);
            uint2 u = *reinterpret_cast<const uint2*>(Hsrc + (size_t)s * 512 + (lane << 2));
            float2 p0 = __half22float2(*reinterpret_cast<__half2*>(&u.x));
            float2 p1 = __half22float2(*reinterpret_cast<__half2*>(&u.y));
            a0 += p0.x; a1 += p0.y; a2 += p1.x; a3 += p1.y;
        }
    }
    float inv = (cnt > 0) ? (1.0f / (float)cnt) : 1.0f;
    a0 *= inv; a1 *= inv; a2 *= inv; a3 *= inv;
    uint2 hi, lo;
    split2(a0, a1, hi.x, lo.x);
    split2(a2, a3, hi.y, lo.y);
    *reinterpret_cast<uint2*>(Adst + (size_t)node * 512 + 256 + (lane << 2)) = hi;
    *reinterpret_cast<uint2*>(Adst + (size_t)node * 512 + 384 + (lane << 2)) = lo;
}

// ------------------------- X -> A1' self blocks ----------------------------
__global__ void k_convertX(const float* __restrict__ x, __half* __restrict__ A) {
    int idx = blockIdx.x * blockDim.x + threadIdx.x;
    if (idx >= NN * 32) return;
    int row = idx >> 5;
    int c = (idx & 31) << 2;
    float4 v = *reinterpret_cast<const float4*>(x + (size_t)row * F + c);
    uint2 hi, lo;
    split2(v.x, v.y, hi.x, lo.x);
    split2(v.z, v.w, hi.y, lo.y);
    *reinterpret_cast<uint2*>(A + (size_t)row * 512 + c) = hi;         // Xh
    *reinterpret_cast<uint2*>(A + (size_t)row * 512 + 128 + c) = lo;   // Xl
}

// ------------------------- weight prep (transpose, fp16) ------------------
__global__ void k_prepW(const float* __restrict__ Ws1, const float* __restrict__ Wn1,
                        const float* __restrict__ Ws2, const float* __restrict__ Wn2,
                        const float* __restrict__ Wo) {
    int k = blockIdx.x;   // 0..127
    int n = threadIdx.x;  // 0..127
    g_B1[n * 256 + k]       = __float2half_rn(Ws1[k * 128 + n]);
    g_B1[n * 256 + 128 + k] = __float2half_rn(Wn1[k * 128 + n]);
    g_B2[n * 256 + k]       = __float2half_rn(Ws2[k * 128 + n]);
    g_B2[n * 256 + 128 + k] = __float2half_rn(Wn2[k * 128 + n]);
    if (n < 64) g_Bc[n * 128 + k] = __float2half_rn(Wo[k * 64 + n]);
}

// ------------------------- warp-MMA GEMM -----------------------------------
// D[128, N] = sum over NIT K=64 chunks of A_chunk @ B_chunk^T, bias (+relu).
// B' (NBCH chunks) fully resident in smem; A double-buffered.
// EPI: 1 = relu, fp16 hi/lo to outA (row stride OSTR, lo at +128)
//      2 = none, fp32 to outF (row stride 64)
template <int N, int NIT, int NBCH, int ASTR, int BSTR, int EPI, int OSTR>
__global__ __launch_bounds__(256) void k_gemm_mma(
    const __half* __restrict__ A, const __half* __restrict__ B,
    const float* __restrict__ bias, float* __restrict__ outF,
    __half* __restrict__ outA, int M)
{
    constexpr int WM = (N == 128) ? 2 : 1;
    constexpr int AT = 128 * 128;        // bytes per A stage
    constexpr int BT = N * 128;          // bytes per B chunk
    extern __shared__ char smem[];
    float* s_bias = reinterpret_cast<float*>(smem);
    const uint32_t sA0 = smem_u32(smem + 512);
    const uint32_t sB0 = sA0 + 2 * AT;   // resident B, NBCH chunks

    const int tid = threadIdx.x;
    const int wid = tid >> 5, lane = tid & 31;
    const int wm = (N == 128) ? (wid >> 1) : wid;
    const int wn = (N == 128) ? (wid & 1) : 0;
    const int row0 = blockIdx.x * 128;

    if (tid < N) s_bias[tid] = bias[tid];

    const int* aC = (NIT == 8) ? c_aL : c_aK;
    const int* bC = (NIT == 8) ? c_bL : c_bK;
    const char* Ab = reinterpret_cast<const char*>(A);
    const char* Bb = reinterpret_cast<const char*>(B);
    const int g = lane >> 3, lr = lane & 7;

    float acc[WM][8][4];
#pragma unroll
    for (int i = 0; i < WM; i++)
#pragma unroll
        for (int j = 0; j < 8; j++)
#pragma unroll
            for (int k = 0; k < 4; k++) acc[i][j][k] = 0.f;

    auto load_A = [&](int i) {
        const uint32_t sa = sA0 + (i & 1) * AT;
        const int ca = aC[i];
#pragma unroll
        for (int t = 0; t < 4; t++) {
            int idx = tid + t * 256;
            int m = idx >> 3, u = idx & 7;
            int r = row0 + m; if (r >= M) r = M - 1;
            cp16(sa + m * 128 + ((u ^ (m & 7)) << 4),
                 Ab + ((size_t)r * ASTR + ca * 64 + u * 8) * 2);
        }
        CP_COMMIT();
    };

    // stage 0: all of B + A chunk 0 (group 0), then A chunk 1 (group 1)
    {
        constexpr int TOT = NBCH * N * 8;
#pragma unroll
        for (int t = 0; t < TOT / 256; t++) {
            int idx = tid + t * 256;
            int ch = idx / (N * 8);
            int rem = idx % (N * 8);
            int n = rem >> 3, u = rem & 7;
            cp16(sB0 + ch * BT + n * 128 + ((u ^ (n & 7)) << 4),
                 Bb + ((size_t)n * BSTR + ch * 64 + u * 8) * 2);
        }
    }
    load_A(0);  // commits B + A0 together? no: commit inside load_A covers both (issued before)

    for (int i = 0; i < NIT; i++) {
        if (i + 1 < NIT) { load_A(i + 1); CP_WAIT(1); }
        else { CP_WAIT(0); }
        __syncthreads();
        const uint32_t sa = sA0 + (i & 1) * AT;
        const uint32_t sbb = sB0 + bC[i] * BT;
#pragma unroll
        for (int kk = 0; kk < 4; kk++) {
            uint32_t a[WM][4];
#pragma unroll
            for (int mt = 0; mt < WM; mt++) {
                int row = wm * (WM * 16) + mt * 16 + (g & 1) * 8 + lr;
                int u = kk * 2 + (g >> 1);
                ldmx4(sa + row * 128 + ((u ^ (row & 7)) << 4),
                      a[mt][0], a[mt][1], a[mt][2], a[mt][3]);
            }
            uint32_t b[4][4];
#pragma unroll
            for (int j = 0; j < 4; j++) {
                int n = wn * 64 + j * 16 + (g >> 1) * 8 + lr;
                int u = kk * 2 + (g & 1);
                ldmx4(sbb + n * 128 + ((u ^ (n & 7)) << 4),
                      b[j][0], b[j][1], b[j][2], b[j][3]);
            }
#pragma unroll
            for (int mt = 0; mt < WM; mt++)
#pragma unroll
                for (int nt = 0; nt < 8; nt++)
                    mma16816(acc[mt][nt],
                             a[mt][0], a[mt][1], a[mt][2], a[mt][3],
                             b[nt >> 1][(nt & 1) * 2], b[nt >> 1][(nt & 1) * 2 + 1]);
        }
        __syncthreads();
    }

    // epilogue
    const int qr = lane >> 2, qc = (lane & 3) << 1;
#pragma unroll
    for (int mt = 0; mt < WM; mt++) {
#pragma unroll
        for (int h = 0; h < 2; h++) {
            int row = row0 + wm * (WM * 16) + mt * 16 + h * 8 + qr;
            if (row >= M) continue;
#pragma unroll
            for (int nt = 0; nt < 8; nt++) {
                int col = wn * 64 + nt * 8 + qc;
                float v0 = acc[mt][nt][h * 2 + 0] + s_bias[col];
                float v1 = acc[mt][nt][h * 2 + 1] + s_bias[col + 1];
                if (EPI == 1) {
                    v0 = fmaxf(v0, 0.f); v1 = fmaxf(v1, 0.f);
                    uint32_t hi, lo;
                    split2(v0, v1, hi, lo);
                    *reinterpret_cast<uint32_t*>(outA + (size_t)row * OSTR + col) = hi;
                    *reinterpret_cast<uint32_t*>(outA + (size_t)row * OSTR + 128 + col) = lo;
                } else {
                    float2 f2 = {v0, v1};
                    *reinterpret_cast<float2*>(outF + (size_t)row * 64 + col) = f2;
                }
            }
        }
    }
}

// ------------------------- launch ------------------------------------------
extern "C" void kernel_launch(void* const* d_in, const int* in_sizes, int n_in,
                              void* d_out, int out_size) {
    const float* x       = (const float*)d_in[0];
    const float* Wself1  = (const float*)d_in[1];
    const float* Wneigh1 = (const float*)d_in[2];
    const float* b1      = (const float*)d_in[3];
    const float* Wself2  = (const float*)d_in[4];
    const float* Wneigh2 = (const float*)d_in[5];
    const float* b2      = (const float*)d_in[6];
    const float* Wout    = (const float*)d_in[7];
    const float* bout    = (const float*)d_in[8];
    const int* edge_src  = (const int*)d_in[9];
    const int* edge_dst  = (const int*)d_in[10];
    float* out = (float*)d_out;

    const int M = in_sizes[0] / F;      // 100000
    const int E = in_sizes[9];          // 1600000
    const int NB = (M + 1023) / 1024;
    const int GB = (M + 127) / 128;     // 782
    const int AGGB = (M * 32 + 255) / 256;

    __half *A1, *A2, *B1, *B2, *Bc;
    int* degp;
    cudaGetSymbolAddress((void**)&A1, g_A1);
    cudaGetSymbolAddress((void**)&A2, g_A2);
    cudaGetSymbolAddress((void**)&B1, g_B1);
    cudaGetSymbolAddress((void**)&B2, g_B2);
    cudaGetSymbolAddress((void**)&Bc, g_Bc);
    cudaGetSymbolAddress((void**)&degp, g_deg);

    const int SMEM_L = 512 + 2 * 16384 + 4 * 128 * 128;  // 98816
    const int SMEM_C = 512 + 2 * 16384 + 2 * 64 * 128;   // 49664
    cudaFuncSetAttribute((const void*)k_gemm_mma<128, 8, 4, 512, 256, 1, 512>,
                         cudaFuncAttributeMaxDynamicSharedMemorySize, SMEM_L);
    cudaFuncSetAttribute((const void*)k_gemm_mma<128, 8, 4, 512, 256, 1, 256>,
                         cudaFuncAttributeMaxDynamicSharedMemorySize, SMEM_L);
    cudaFuncSetAttribute((const void*)k_gemm_mma<64, 4, 2, 256, 128, 2, 0>,
                         cudaFuncAttributeMaxDynamicSharedMemorySize, SMEM_C);

    // CSR build
    cudaMemsetAsync(degp, 0, (size_t)M * sizeof(int), 0);
    k_count_deg<<<(E + 255) / 256, 256>>>(edge_dst, E);
    k_scan1<<<NB, 1024>>>(M);
    k_scan2<<<1, 128>>>(NB);
    k_scan3<<<NB, 1024>>>(M);
    k_scatter<<<(E + 255) / 256, 256>>>(edge_src, edge_dst, E);

    // operand prep
    k_prepW<<<128, 128>>>(Wself1, Wneigh1, Wself2, Wneigh2, Wout);
    k_convertX<<<(NN * 32 + 255) / 256, 256>>>(x, A1);

    // layer 1 aggregation: gather Xh from A1, write G blocks of A1
    k_agg<<<AGGB, 256>>>(A1, A1);

    // layer 1 GEMM: writes A2 self blocks [Hh|Hl] (stride 512)
    k_gemm_mma<128, 8, 4, 512, 256, 1, 512><<<GB, 256, SMEM_L>>>(A1, B1, b1, nullptr, A2, M);

    // layer 2 aggregation: gather Hh from A2, write G blocks of A2
    k_agg<<<AGGB, 256>>>(A2, A2);

    // layer 2 GEMM: writes classifier A' into A1 (stride 256)
    k_gemm_mma<128, 8, 4, 512, 256, 1, 256><<<GB, 256, SMEM_L>>>(A2, B2, b2, nullptr, A1, M);

    // classifier
    k_gemm_mma<64, 4, 2, 256, 128, 2, 0><<<GB, 256, SMEM_C>>>(A1, Bc, bout, out, nullptr, M);
}